// round 2
// baseline (speedup 1.0000x reference)
#include <cuda_runtime.h>
#include <cuda_bf16.h>
#include <cstdint>
#include <cstddef>

// ---------------------------------------------------------------------------
// Problem dims
// ---------------------------------------------------------------------------
#define M_DIM 8192
#define N_DIM 4096
#define K_DIM 4096

// GEMM tiling
#define BM 128
#define BN 128
#define BK 64                    // bf16 elems per K-tile = 128 bytes/row
#define STAGES 3
#define KT (K_DIM / BK)          // 64
#define GEMM_THREADS 256         // 8 warps: 2 (M) x 4 (N), warp tile 64x32

#define A_TILE_BYTES (BM * 128)                       // 16 KB (one of hi/lo)
#define B_TILE_BYTES (BN * 128)                       // 16 KB
#define STAGE_BYTES  (2 * A_TILE_BYTES + B_TILE_BYTES) // 48 KB
#define SMEM_TOTAL   (STAGES * STAGE_BYTES)            // 144 KB

// ---------------------------------------------------------------------------
// Device scratch (allocation-free rule: __device__ globals)
// ---------------------------------------------------------------------------
__device__ float g_partials[1024];
__device__ float g_thr;
__device__ __nv_bfloat16 g_q  [(size_t)N_DIM * K_DIM]; // 32 MB ternary weights (exact)
__device__ __nv_bfloat16 g_xhi[(size_t)M_DIM * K_DIM]; // 64 MB
__device__ __nv_bfloat16 g_xlo[(size_t)M_DIM * K_DIM]; // 64 MB

// ---------------------------------------------------------------------------
// Helpers
// ---------------------------------------------------------------------------
__device__ __forceinline__ uint32_t smem_u32(const void* p) {
    return (uint32_t)__cvta_generic_to_shared(p);
}

__device__ __forceinline__ void cp16(uint32_t dst, const void* src) {
    asm volatile("cp.async.cg.shared.global [%0], [%1], 16;" :: "r"(dst), "l"(src));
}

__device__ __forceinline__ void ldsm_x4(uint32_t (&r)[4], uint32_t addr) {
    asm volatile("ldmatrix.sync.aligned.m8n8.x4.shared.b16 {%0,%1,%2,%3}, [%4];"
                 : "=r"(r[0]), "=r"(r[1]), "=r"(r[2]), "=r"(r[3]) : "r"(addr));
}

__device__ __forceinline__ void mma16816(float (&c)[4], const uint32_t (&a)[4],
                                         uint32_t b0, uint32_t b1) {
    asm volatile(
        "mma.sync.aligned.m16n8k16.row.col.f32.bf16.bf16.f32 "
        "{%0,%1,%2,%3}, {%4,%5,%6,%7}, {%8,%9}, {%0,%1,%2,%3};"
        : "+f"(c[0]), "+f"(c[1]), "+f"(c[2]), "+f"(c[3])
        : "r"(a[0]), "r"(a[1]), "r"(a[2]), "r"(a[3]), "r"(b0), "r"(b1));
}

// ---------------------------------------------------------------------------
// Prep kernels: threshold reduction, ternary quantize -> bf16, hi/lo split
// ---------------------------------------------------------------------------
__global__ void k_abs_partial(const float* __restrict__ w) {
    const float4* w4 = (const float4*)w;
    const int n4 = (N_DIM * K_DIM) / 4;
    float s = 0.0f;
    for (int i = blockIdx.x * blockDim.x + threadIdx.x; i < n4; i += gridDim.x * blockDim.x) {
        float4 v = w4[i];
        s += fabsf(v.x) + fabsf(v.y) + fabsf(v.z) + fabsf(v.w);
    }
    __shared__ float sm[256];
    sm[threadIdx.x] = s;
    __syncthreads();
    for (int o = 128; o > 0; o >>= 1) {
        if (threadIdx.x < o) sm[threadIdx.x] += sm[threadIdx.x + o];
        __syncthreads();
    }
    if (threadIdx.x == 0) g_partials[blockIdx.x] = sm[0];
}

__global__ void k_thr() {
    __shared__ float sm[1024];
    sm[threadIdx.x] = g_partials[threadIdx.x];
    __syncthreads();
    for (int o = 512; o > 0; o >>= 1) {
        if (threadIdx.x < o) sm[threadIdx.x] += sm[threadIdx.x + o];
        __syncthreads();
    }
    if (threadIdx.x == 0)
        g_thr = 0.05f * (sm[0] / (float)((size_t)N_DIM * K_DIM));
}

__device__ __forceinline__ uint32_t pack2bf(float a, float b) {
    __nv_bfloat162 t = __floats2bfloat162_rn(a, b);
    union { __nv_bfloat162 h; uint32_t u; } cv;
    cv.h = t;
    return cv.u;
}

__device__ __forceinline__ float tq(float v, float thr) {
    return v > thr ? 1.0f : (v < -thr ? -1.0f : 0.0f);
}

__global__ void k_quant(const float* __restrict__ w) {
    const float thr = g_thr;
    const float4* w4 = (const float4*)w;
    uint2* q4 = (uint2*)g_q;
    const int n4 = (N_DIM * K_DIM) / 4;
    for (int i = blockIdx.x * blockDim.x + threadIdx.x; i < n4; i += gridDim.x * blockDim.x) {
        float4 v = w4[i];
        uint2 o;
        o.x = pack2bf(tq(v.x, thr), tq(v.y, thr));
        o.y = pack2bf(tq(v.z, thr), tq(v.w, thr));
        q4[i] = o;
    }
}

__global__ void k_split(const float* __restrict__ x) {
    const float4* x4 = (const float4*)x;
    uint2* hi4 = (uint2*)g_xhi;
    uint2* lo4 = (uint2*)g_xlo;
    const int n4 = (M_DIM * K_DIM) / 4;
    for (int i = blockIdx.x * blockDim.x + threadIdx.x; i < n4; i += gridDim.x * blockDim.x) {
        float4 v = x4[i];
        float h0 = __bfloat162float(__float2bfloat16_rn(v.x));
        float h1 = __bfloat162float(__float2bfloat16_rn(v.y));
        float h2 = __bfloat162float(__float2bfloat16_rn(v.z));
        float h3 = __bfloat162float(__float2bfloat16_rn(v.w));
        uint2 hv, lv;
        hv.x = pack2bf(h0, h1);
        hv.y = pack2bf(h2, h3);
        lv.x = pack2bf(v.x - h0, v.y - h1);
        lv.y = pack2bf(v.z - h2, v.w - h3);
        hi4[i] = hv;
        lo4[i] = lv;
    }
}

// ---------------------------------------------------------------------------
// GEMM: out = xhi @ q^T + xlo @ q^T  via mma.sync m16n8k16 bf16 (fp32 accum)
//   3-stage cp.async pipeline; q tile shared by both hi and lo passes.
// ---------------------------------------------------------------------------
__global__ void __launch_bounds__(GEMM_THREADS, 1)
k_gemm(float* __restrict__ out) {
    extern __shared__ char smem[];
    const uint32_t sb = smem_u32(smem);
    const int tid  = threadIdx.x;
    const int wid  = tid >> 5;
    const int lane = tid & 31;
    const int warp_m = wid & 1;   // 0..1 -> 64 rows each
    const int warp_n = wid >> 1;  // 0..3 -> 32 cols each
    const int m0 = blockIdx.y * BM;
    const int n0 = blockIdx.x * BN;

    // ---- async tile loader (XOR-swizzled 16B chunks, 128B rows) ----
    auto load_stage = [&](int kt, int st) {
        const uint32_t base = sb + st * STAGE_BYTES;
        const size_t kofs = (size_t)kt * BK;
        #pragma unroll
        for (int i = tid; i < BM * 8; i += GEMM_THREADS) {
            const int r = i >> 3, c = i & 7;
            const uint32_t d = base + r * 128 + ((c ^ (r & 7)) << 4);
            const size_t g = (size_t)(m0 + r) * K_DIM + kofs + c * 8;
            cp16(d, &g_xhi[g]);
            cp16(d + A_TILE_BYTES, &g_xlo[g]);
        }
        #pragma unroll
        for (int i = tid; i < BN * 8; i += GEMM_THREADS) {
            const int r = i >> 3, c = i & 7;
            const uint32_t d = base + 2 * A_TILE_BYTES + r * 128 + ((c ^ (r & 7)) << 4);
            cp16(d, &g_q[(size_t)(n0 + r) * K_DIM + kofs + c * 8]);
        }
        asm volatile("cp.async.commit_group;" ::: "memory");
    };

    float acc[4][4][4];   // [mi][ni][frag]
    #pragma unroll
    for (int mi = 0; mi < 4; mi++)
        #pragma unroll
        for (int ni = 0; ni < 4; ni++)
            #pragma unroll
            for (int j = 0; j < 4; j++) acc[mi][ni][j] = 0.0f;

    // precomputed ldmatrix smem offsets (lane-dependent, stage-relative)
    // A: row = warp_m*64 + mi*16 + (lane%16), k-chunk-half = lane/16
    const int a_row  = warp_m * 64 + (lane & 15);
    const int a_half = lane >> 4;                       // 0/1 -> +8 k
    // B: n = warp_n*32 + jt*16 + (lane%8) + 8*(lane/16), k-half = (lane>>3)&1
    const int b_row  = warp_n * 32 + (lane & 7) + ((lane >> 4) << 3);
    const int b_half = (lane >> 3) & 1;

    // prologue
    #pragma unroll
    for (int j = 0; j < STAGES - 1; j++) load_stage(j, j);

    for (int it = 0; it < KT; it++) {
        const int st = it % STAGES;
        asm volatile("cp.async.wait_group %0;" :: "n"(STAGES - 2) : "memory");
        __syncthreads();

        const uint32_t abase_hi = sb + st * STAGE_BYTES;
        const uint32_t abase_lo = abase_hi + A_TILE_BYTES;
        const uint32_t bbase    = abase_hi + 2 * A_TILE_BYTES;

        #pragma unroll
        for (int ks = 0; ks < 4; ks++) {  // 4 x k16 covers BK=64
            // B frags: 2 x ldmatrix.x4 -> 4 n8-frags
            uint32_t bfr[4][2];
            #pragma unroll
            for (int jt = 0; jt < 2; jt++) {
                const int n = b_row + jt * 16;
                const int ch = ks * 2 + b_half;
                uint32_t r4[4];
                ldsm_x4(r4, bbase + n * 128 + (((ch) ^ (n & 7)) << 4));
                bfr[2 * jt + 0][0] = r4[0]; bfr[2 * jt + 0][1] = r4[1];
                bfr[2 * jt + 1][0] = r4[2]; bfr[2 * jt + 1][1] = r4[3];
            }
            // A hi frags + MMA
            #pragma unroll
            for (int mi = 0; mi < 4; mi++) {
                const int r = a_row + mi * 16;
                const int ch = ks * 2 + a_half;
                uint32_t a4[4];
                ldsm_x4(a4, abase_hi + r * 128 + ((ch ^ (r & 7)) << 4));
                #pragma unroll
                for (int ni = 0; ni < 4; ni++)
                    mma16816(acc[mi][ni], a4, bfr[ni][0], bfr[ni][1]);
            }
            // A lo frags + MMA (same B frags)
            #pragma unroll
            for (int mi = 0; mi < 4; mi++) {
                const int r = a_row + mi * 16;
                const int ch = ks * 2 + a_half;
                uint32_t a4[4];
                ldsm_x4(a4, abase_lo + r * 128 + ((ch ^ (r & 7)) << 4));
                #pragma unroll
                for (int ni = 0; ni < 4; ni++)
                    mma16816(acc[mi][ni], a4, bfr[ni][0], bfr[ni][1]);
            }
        }

        if (it + STAGES - 1 < KT) load_stage(it + STAGES - 1, (it + STAGES - 1) % STAGES);
        else asm volatile("cp.async.commit_group;" ::: "memory"); // keep group count in sync
    }

    // ---- epilogue: direct float2 stores ----
    // c0,c1 -> (row lane/4,   col 2*(lane%4)); c2,c3 -> (row lane/4+8, same col)
    const int er = lane >> 2;
    const int ec = (lane & 3) * 2;
    #pragma unroll
    for (int mi = 0; mi < 4; mi++) {
        #pragma unroll
        for (int ni = 0; ni < 4; ni++) {
            const int row = m0 + warp_m * 64 + mi * 16 + er;
            const int col = n0 + warp_n * 32 + ni * 8 + ec;
            float2 v0 = make_float2(acc[mi][ni][0], acc[mi][ni][1]);
            float2 v1 = make_float2(acc[mi][ni][2], acc[mi][ni][3]);
            *(float2*)&out[(size_t)row * N_DIM + col] = v0;
            *(float2*)&out[(size_t)(row + 8) * N_DIM + col] = v1;
        }
    }
}

// ---------------------------------------------------------------------------
// Launch
// ---------------------------------------------------------------------------
extern "C" void kernel_launch(void* const* d_in, const int* in_sizes, int n_in,
                              void* d_out, int out_size) {
    const float* x = (const float*)d_in[0];   // [8192, 4096]
    const float* w = (const float*)d_in[1];   // [4096, 4096]
    float* out = (float*)d_out;               // [8192, 4096]

    cudaFuncSetAttribute(k_gemm, cudaFuncAttributeMaxDynamicSharedMemorySize, SMEM_TOTAL);

    k_abs_partial<<<1024, 256>>>(w);
    k_thr<<<1, 1024>>>();
    k_quant<<<4096, 256>>>(w);
    k_split<<<8192, 256>>>(x);

    // N-blocks fast: a concurrent wave shares q (32 MB, L2-resident)
    dim3 grid(N_DIM / BN, M_DIM / BM);
    k_gemm<<<grid, GEMM_THREADS, SMEM_TOTAL>>>(out);
}